// round 15
// baseline (speedup 1.0000x reference)
#include <cuda_runtime.h>
#include <cuda_fp16.h>
#include <math.h>
#include <stdint.h>

// B=2, S=4096, HID=2048, H=16, KV=4, D=128, BS=64, L=4, G=4, STRIDE=4, WTOK=2048
#define NEGV (-1000000000.0f)
#define SCALEV 0.08838834764831845f   // 1/sqrt(128)

// ---------------- scratch (__device__ globals; allocation-free rule) -------
// Q/K stored in PERMUTED-d layout within each head: p=2j <-> d=j, p=2j+1 <-> d=j+64.
__device__ __align__(1024) __half g_Qh [2 * 4096 * 2048];
__device__ __align__(1024) __half g_Kh [2 * 4096 * 512];
__device__ __align__(1024) __half g_Vh [2 * 4096 * 512];
__device__ __align__(1024) __half g_AOh[2 * 4096 * 2048];
__device__ __align__(1024) __half g_Xh [2 * 4096 * 2048];
__device__ __align__(1024) __half g_WqT[2048 * 2048];
__device__ __align__(1024) __half g_WkT[512 * 2048];
__device__ __align__(1024) __half g_WvT[512 * 2048];
__device__ __align__(1024) __half g_WoT[2048 * 2048];

// ---------------- helpers ---------------------------------------------------
__device__ __forceinline__ uint32_t smem_u32(const void* p) {
    uint32_t a;
    asm("{ .reg .u64 t; cvta.to.shared.u64 t, %1; cvt.u32.u64 %0, t; }" : "=r"(a) : "l"(p));
    return a;
}
#define CP_ASYNC16(sm, gm) \
    asm volatile("cp.async.cg.shared.global [%0], [%1], 16;" :: "r"(sm), "l"(gm) : "memory")
#define CP_COMMIT() asm volatile("cp.async.commit_group;" ::: "memory")
#define CP_WAIT0()  asm volatile("cp.async.wait_group 0;" ::: "memory")
#define CP_WAIT1()  asm volatile("cp.async.wait_group 1;" ::: "memory")

__device__ __forceinline__ void mma_f16(float c[4], const uint32_t a[4], uint32_t b0, uint32_t b1) {
    asm volatile(
        "mma.sync.aligned.m16n8k16.row.col.f32.f16.f16.f32 "
        "{%0,%1,%2,%3}, {%4,%5,%6,%7}, {%8,%9}, {%0,%1,%2,%3};"
        : "+f"(c[0]), "+f"(c[1]), "+f"(c[2]), "+f"(c[3])
        : "r"(a[0]), "r"(a[1]), "r"(a[2]), "r"(a[3]), "r"(b0), "r"(b1));
}
__device__ __forceinline__ void ldsm4(uint32_t r[4], uint32_t addr) {
    asm volatile("ldmatrix.sync.aligned.m8n8.x4.shared.b16 {%0,%1,%2,%3}, [%4];"
                 : "=r"(r[0]), "=r"(r[1]), "=r"(r[2]), "=r"(r[3]) : "r"(addr));
}
__device__ __forceinline__ void ldsm4t(uint32_t r[4], uint32_t addr) {
    asm volatile("ldmatrix.sync.aligned.m8n8.x4.trans.shared.b16 {%0,%1,%2,%3}, [%4];"
                 : "=r"(r[0]), "=r"(r[1]), "=r"(r[2]), "=r"(r[3]) : "r"(addr));
}
__device__ __forceinline__ uint32_t packh2(float x, float y) {
    __half2 h = __floats2half2_rn(x, y);
    return *(uint32_t*)&h;
}

// ---------------------------------------------------------------------------
// GEMM core: 128x128 CTA tile, 4 warps, warp tile 64x64, BK=64, 3-stage
// cp.async. Pitch 72 halves (144B): conflict-free ldmatrix (validated R9).
// smem = 3 stages * 2 matrices * 128*72*2B = 110592 B -> 2 CTAs/SM.
// ---------------------------------------------------------------------------
#define HP2  72
#define STGH (128 * HP2)                      // halves per matrix per stage
#define GSMH_BYTES (6 * STGH * 2)             // 110592 B

#define GLOADH(buf, k0)                                                                \
    do {                                                                               \
        _Pragma("unroll")                                                              \
        for (int it = 0; it < 8; it++) {                                               \
            const int row = ldrow + it * 16;                                           \
            const uint32_t so = (uint32_t)(((buf) * STGH + row * HP2 + ldc * 8) * 2);  \
            CP_ASYNC16(smbA + so, A  + (size_t)(crow0 + row) * K + (k0) + ldc * 8);    \
            CP_ASYNC16(smbB + so, Bt + (size_t)(ccol0 + row) * K + (k0) + ldc * 8);    \
        }                                                                              \
    } while (0)

#define GEMM_MAIN(T)                                                                   \
    GLOADH(0, 0);  CP_COMMIT();                                                        \
    GLOADH(1, 64); CP_COMMIT();                                                        \
    int buf = 0;                                                                       \
    for (int t = 0; t < (T); t++) {                                                    \
        if (t + 1 < (T)) CP_WAIT1(); else CP_WAIT0();                                  \
        __syncthreads();                                                               \
        if (t + 2 < (T)) {                                                             \
            const int nb = (buf + 2 >= 3) ? (buf - 1) : (buf + 2);                     \
            GLOADH(nb, (t + 2) << 6); CP_COMMIT();                                     \
        }                                                                              \
        const uint32_t Ab = smbA + buf * STGH * 2;                                     \
        const uint32_t Bb = smbB + buf * STGH * 2;                                     \
        _Pragma("unroll")                                                              \
        for (int kk = 0; kk < 4; kk++) {                                               \
            uint32_t a[4][4];                                                          \
            _Pragma("unroll")                                                          \
            for (int mt = 0; mt < 4; mt++)                                             \
                ldsm4(a[mt], Ab + ((aRowBase + mt * 16) * HP2 + kk * 16 + aKoff) * 2); \
            uint32_t br[4][4];                                                         \
            _Pragma("unroll")                                                          \
            for (int g = 0; g < 4; g++)                                                \
                ldsm4(br[g], Bb + ((bRowBase + g * 16) * HP2 + kk * 16 + bKoff) * 2);  \
            _Pragma("unroll")                                                          \
            for (int mt = 0; mt < 4; mt++)                                             \
                _Pragma("unroll")                                                      \
                for (int nt = 0; nt < 8; nt++)                                         \
                    mma_f16(acc[mt][nt], a[mt], br[nt >> 1][(nt & 1) * 2],             \
                            br[nt >> 1][(nt & 1) * 2 + 1]);                            \
        }                                                                              \
        buf = (buf + 1 >= 3) ? 0 : (buf + 1);                                          \
    }

// ---------------------------------------------------------------------------
// Fused QKV projection GEMM + RoPE epilogue (Q,K regions; V plain).
// grid.x: 0-15 Q | 16-19 K | 20-23 V. grid.y: 64 row tiles. 128 threads.
// ---------------------------------------------------------------------------
__global__ __launch_bounds__(128, 2) void gemm_qkv(
    const __half* __restrict__ A,
    const __half* __restrict__ WqT_, const __half* __restrict__ WkT_,
    const __half* __restrict__ WvT_,
    __half* __restrict__ Qh, __half* __restrict__ Kh, __half* __restrict__ Vh,
    const float* __restrict__ cosp, const float* __restrict__ sinp)
{
    extern __shared__ __half smh[];
    const uint32_t smbA = smem_u32(smh);
    const uint32_t smbB = smbA + 3 * STGH * 2;

    const int bx = blockIdx.x;
    const __half* Bt;
    __half* C;
    int Nc, ccol0;
    bool rope;
    if (bx < 16)      { Bt = WqT_; C = Qh; Nc = 2048; ccol0 = bx * 128;        rope = true;  }
    else if (bx < 20) { Bt = WkT_; C = Kh; Nc = 512;  ccol0 = (bx - 16) * 128; rope = true;  }
    else              { Bt = WvT_; C = Vh; Nc = 512;  ccol0 = (bx - 20) * 128; rope = false; }
    const int K = 2048;

    const int tid  = threadIdx.x;
    const int lane = tid & 31;
    const int warp = tid >> 5;
    const int wm = warp & 1;
    const int wn = warp >> 1;
    const int lr = lane >> 2;
    const int lc = lane & 3;
    const int crow0 = blockIdx.y * 128;

    const int ldrow = tid >> 3;           // 0..15
    const int ldc   = tid & 7;            // 0..7 (8-half chunks in 64-half row)

    float acc[4][8][4];
#pragma unroll
    for (int mt = 0; mt < 4; mt++)
#pragma unroll
        for (int nt = 0; nt < 8; nt++)
#pragma unroll
            for (int i = 0; i < 4; i++) acc[mt][nt][i] = 0.f;

    const int aRowBase = wm * 64 + (lane & 15);
    const int aKoff    = (lane >> 4) * 8;
    const int bRowBase = wn * 64 + (lane & 7) + ((lane >> 4) & 1) * 8;
    const int bKoff    = ((lane >> 3) & 1) * 8;

    GEMM_MAIN(32)   // K=2048 / 64

    if (rope) {
#pragma unroll
        for (int mt = 0; mt < 4; mt++) {
            const int r0 = crow0 + wm * 64 + mt * 16 + lr;
#pragma unroll
            for (int nt = 0; nt < 8; nt++) {
                const int col = ccol0 + wn * 64 + nt * 8 + 2 * lc;
                const int d = (col & 127) >> 1;
                {
                    const float c1 = __ldg(cosp + (size_t)r0 * 128 + d);
                    const float s1 = __ldg(sinp + (size_t)r0 * 128 + d);
                    const float c2 = __ldg(cosp + (size_t)r0 * 128 + d + 64);
                    const float s2 = __ldg(sinp + (size_t)r0 * 128 + d + 64);
                    const float a0 = acc[mt][nt][0], a1 = acc[mt][nt][1];
                    *(uint32_t*)(C + (size_t)r0 * Nc + col) =
                        packh2(a0 * c1 - a1 * s1, a1 * c2 + a0 * s2);
                }
                {
                    const int r1 = r0 + 8;
                    const float c1 = __ldg(cosp + (size_t)r1 * 128 + d);
                    const float s1 = __ldg(sinp + (size_t)r1 * 128 + d);
                    const float c2 = __ldg(cosp + (size_t)r1 * 128 + d + 64);
                    const float s2 = __ldg(sinp + (size_t)r1 * 128 + d + 64);
                    const float a0 = acc[mt][nt][2], a1 = acc[mt][nt][3];
                    *(uint32_t*)(C + (size_t)r1 * Nc + col) =
                        packh2(a0 * c1 - a1 * s1, a1 * c2 + a0 * s2);
                }
            }
        }
    } else {
#pragma unroll
        for (int mt = 0; mt < 4; mt++) {
            const int row = crow0 + wm * 64 + mt * 16 + lr;
#pragma unroll
            for (int nt = 0; nt < 8; nt++) {
                const int col = ccol0 + wn * 64 + nt * 8 + 2 * lc;
                *(uint32_t*)(C + (size_t)row * Nc + col)       = packh2(acc[mt][nt][0], acc[mt][nt][1]);
                *(uint32_t*)(C + (size_t)(row + 8) * Nc + col) = packh2(acc[mt][nt][2], acc[mt][nt][3]);
            }
        }
    }
}

// ---------------------------------------------------------------------------
// Output projection GEMM (fp32 out).
// ---------------------------------------------------------------------------
__global__ __launch_bounds__(128, 2) void gemm_wo(
    const __half* __restrict__ A, const __half* __restrict__ Bt, float* __restrict__ C,
    int M, int N, int K)
{
    extern __shared__ __half smh[];
    const uint32_t smbA = smem_u32(smh);
    const uint32_t smbB = smbA + 3 * STGH * 2;

    const int tid  = threadIdx.x;
    const int lane = tid & 31;
    const int warp = tid >> 5;
    const int wm = warp & 1;
    const int wn = warp >> 1;
    const int lr = lane >> 2;
    const int lc = lane & 3;
    const int crow0 = blockIdx.y * 128;
    const int ccol0 = blockIdx.x * 128;

    const int ldrow = tid >> 3;
    const int ldc   = tid & 7;

    float acc[4][8][4];
#pragma unroll
    for (int mt = 0; mt < 4; mt++)
#pragma unroll
        for (int nt = 0; nt < 8; nt++)
#pragma unroll
            for (int i = 0; i < 4; i++) acc[mt][nt][i] = 0.f;

    const int aRowBase = wm * 64 + (lane & 15);
    const int aKoff    = (lane >> 4) * 8;
    const int bRowBase = wn * 64 + (lane & 7) + ((lane >> 4) & 1) * 8;
    const int bKoff    = ((lane >> 3) & 1) * 8;

    const int T = K >> 6;
    GEMM_MAIN(T)

#pragma unroll
    for (int mt = 0; mt < 4; mt++) {
        const int row = crow0 + wm * 64 + mt * 16 + lr;
#pragma unroll
        for (int nt = 0; nt < 8; nt++) {
            const int col = ccol0 + wn * 64 + nt * 8 + 2 * lc;
            *(float2*)(C + (size_t)row * N + col)       = make_float2(acc[mt][nt][0], acc[mt][nt][1]);
            *(float2*)(C + (size_t)(row + 8) * N + col) = make_float2(acc[mt][nt][2], acc[mt][nt][3]);
        }
    }
}

// ---------------------------------------------------------------------------
// prep kernels
// ---------------------------------------------------------------------------
__global__ void round_half(const float* __restrict__ src, __half* __restrict__ dst, int n8) {
    int i = blockIdx.x * blockDim.x + threadIdx.x;
    if (i < n8) {
        float4 v0 = ((const float4*)src)[2 * i];
        float4 v1 = ((const float4*)src)[2 * i + 1];
        uint4 o;
        o.x = packh2(v0.x, v0.y); o.y = packh2(v0.z, v0.w);
        o.z = packh2(v1.x, v1.y); o.w = packh2(v1.z, v1.w);
        ((uint4*)dst)[i] = o;
    }
}
// All four weight transposes in one launch. blockIdx.z: 0=Wq(perm) 1=Wk(perm)
// 2=Wv 3=Wo. K=2048 rows for all; N=2048 for Wq/Wo, 512 for Wk/Wv.
__global__ void transpose_all(const float* __restrict__ Wq, const float* __restrict__ Wk,
                              const float* __restrict__ Wv, const float* __restrict__ Wo,
                              __half* __restrict__ WqT, __half* __restrict__ WkT,
                              __half* __restrict__ WvT, __half* __restrict__ WoT)
{
    const int z = blockIdx.z;
    const float* W; __half* Wt; int N; bool perm;
    if (z == 0)      { W = Wq; Wt = WqT; N = 2048; perm = true;  }
    else if (z == 1) { W = Wk; Wt = WkT; N = 512;  perm = true;  }
    else if (z == 2) { W = Wv; Wt = WvT; N = 512;  perm = false; }
    else             { W = Wo; Wt = WoT; N = 2048; perm = false; }
    const int K = 2048;
    if (blockIdx.x * 32 >= N) return;

    __shared__ float t[32][33];
    const int n0 = blockIdx.x * 32, k0 = blockIdx.y * 32;
    const int x = threadIdx.x, y = threadIdx.y;
#pragma unroll
    for (int j = 0; j < 32; j += 8)
        t[y + j][x] = W[(size_t)(k0 + y + j) * N + n0 + x];
    __syncthreads();
#pragma unroll
    for (int j = 0; j < 32; j += 8) {
        const int n = n0 + y + j;
        int npr = n;
        if (perm) {
            const int d = n & 127;
            const int p = (d < 64) ? (2 * d) : (2 * (d - 64) + 1);
            npr = (n & ~127) | p;
        }
        Wt[(size_t)npr * K + k0 + x] = __float2half_rn(t[x][y + j]);
    }
}

// ---------------------------------------------------------------------------
// Flash-style fp16 block-sparse attention (unchanged from R13 — passing).
// ---------------------------------------------------------------------------
#define AP    136
#define ATILE (64 * AP)
#define SQ_H  0
#define SK_H  ATILE
#define SV_H  (SK_H + 2 * ATILE)
#define ATTN2_SMEM_BYTES ((SV_H + 2 * ATILE) * 2)   // 87040 B

__global__ __launch_bounds__(128, 2) void attn_flash(
    const __half* __restrict__ Q, const __half* __restrict__ K, const __half* __restrict__ V,
    const float* __restrict__ mask, __half* __restrict__ AO)
{
    extern __shared__ __half smA[];
    const uint32_t Qaddr = smem_u32(smA + SQ_H);
    const uint32_t Kaddr = smem_u32(smA + SK_H);
    const uint32_t Vaddr = smem_u32(smA + SV_H);

    const int qb = blockIdx.x;
    const int h  = blockIdx.y;
    const int b  = blockIdx.z;
    const int kvh = h >> 2;
    const int tid = threadIdx.x;
    const int lane = tid & 31;
    const int warp = tid >> 5;
    const int lr = lane >> 2;
    const int lc = lane & 3;
    const int wr = warp * 16;

    int kblk[8]; bool kvalid[8];
#pragma unroll
    for (int w = 0; w < 4; w++) {
        int jb = qb - 3 + w;
        kblk[w] = jb < 0 ? 0 : jb;
        kvalid[w] = (jb >= 0);
    }
    {
        int start = qb - 32; if (start < 0) start = 0;
        int cnt = (qb > start) ? ((qb - start + 3) >> 2) : 0;
        int first = (cnt > 4) ? (cnt - 4) : 0;
        int sz = (cnt < 4) ? cnt : 4;
        int s0 = 4 - sz;
#pragma unroll
        for (int g = 0; g < 4; g++) {
            if (g < s0) { kblk[4 + g] = 0; kvalid[4 + g] = false; }
            else        { kblk[4 + g] = start + 4 * (first + g - s0); kvalid[4 + g] = true; }
        }
    }

    const __half* Qsrc  = Q + (size_t)(b * 4096 + qb * 64) * 2048 + h * 128;
    const __half* Kbase = K + (size_t)b * 4096 * 512 + kvh * 128;
    const __half* Vbase = V + (size_t)b * 4096 * 512 + kvh * 128;

#define AKV_ISSUE(stage, blk)                                                          \
    do {                                                                               \
        const __half* ksrc = Kbase + (size_t)(blk) * 64 * 512;                         \
        const __half* vsrc = Vbase + (size_t)(blk) * 64 * 512;                         \
        _Pragma("unroll")                                                              \
        for (int it = 0; it < 8; it++) {                                               \
            const int f = tid + it * 128;                                              \
            const int row = f >> 4, c8 = f & 15;                                       \
            const uint32_t so = (stage) * (ATILE * 2) + (row * AP + c8 * 8) * 2;       \
            CP_ASYNC16(Kaddr + so, ksrc + (size_t)row * 512 + c8 * 8);                 \
            CP_ASYNC16(Vaddr + so, vsrc + (size_t)row * 512 + c8 * 8);                 \
        }                                                                              \
    } while (0)

#pragma unroll
    for (int it = 0; it < 8; it++) {
        const int f = tid + it * 128;
        const int row = f >> 4, c8 = f & 15;
        CP_ASYNC16(Qaddr + (row * AP + c8 * 8) * 2, Qsrc + (size_t)row * 2048 + c8 * 8);
    }
    AKV_ISSUE(0, kblk[0]);
    CP_COMMIT();
    CP_WAIT0();
    __syncthreads();

    uint32_t qf[8][4];
    const int aRow  = wr + (lane & 15);
    const int aKoff = (lane >> 4) * 8;
#pragma unroll
    for (int kk = 0; kk < 8; kk++)
        ldsm4(qf[kk], Qaddr + (aRow * AP + kk * 16 + aKoff) * 2);

    float o[16][4];
#pragma unroll
    for (int j = 0; j < 16; j++)
#pragma unroll
        for (int i = 0; i < 4; i++) o[j][i] = 0.f;
    float m_lo = -1e30f, m_hi = -1e30f, l_lo = 0.f, l_hi = 0.f;

    const int bRow  = (lane & 7) + ((lane >> 4) & 1) * 8;
    const int bKoff = ((lane >> 3) & 1) * 8;
    const int vKrow = (lane & 7) + ((lane >> 3) & 1) * 8;
    const int vDoff = ((lane >> 4) & 1) * 8;
    const int row_lo = wr + lr;

    for (int s = 0; s < 8; s++) {
        if (s < 7) { AKV_ISSUE((s + 1) & 1, kblk[s + 1]); CP_COMMIT(); }

        if (kvalid[s]) {
            const uint32_t Kst = Kaddr + (s & 1) * (ATILE * 2);
            const uint32_t Vst = Vaddr + (s & 1) * (ATILE * 2);

            float sc[8][4];
#pragma unroll
            for (int nt = 0; nt < 8; nt++)
#pragma unroll
                for (int i = 0; i < 4; i++) sc[nt][i] = 0.f;
#pragma unroll
            for (int kk = 0; kk < 8; kk++) {
                uint32_t br[4][4];
#pragma unroll
                for (int g = 0; g < 4; g++)
                    ldsm4(br[g], Kst + ((g * 16 + bRow) * AP + kk * 16 + bKoff) * 2);
#pragma unroll
                for (int nt = 0; nt < 8; nt++)
                    mma_f16(sc[nt], qf[kk], br[nt >> 1][(nt & 1) * 2], br[nt >> 1][(nt & 1) * 2 + 1]);
            }

            const float* mrow = mask + (size_t)b * 4096 + kblk[s] * 64;
            const bool cz = (s == 3);
#pragma unroll
            for (int nt = 0; nt < 8; nt++) {
                const int c0 = nt * 8 + 2 * lc;
                const float mv0 = (1.0f - __ldg(mrow + c0)) * NEGV;
                const float mv1 = (1.0f - __ldg(mrow + c0 + 1)) * NEGV;
                sc[nt][0] = sc[nt][0] * SCALEV + mv0;
                sc[nt][1] = sc[nt][1] * SCALEV + mv1;
                sc[nt][2] = sc[nt][2] * SCALEV + mv0;
                sc[nt][3] = sc[nt][3] * SCALEV + mv1;
                if (cz) {
                    if (c0     > row_lo)     sc[nt][0] += NEGV;
                    if (c0 + 1 > row_lo)     sc[nt][1] += NEGV;
                    if (c0     > row_lo + 8) sc[nt][2] += NEGV;
                    if (c0 + 1 > row_lo + 8) sc[nt][3] += NEGV;
                }
            }

            float tm_lo = -1e30f, tm_hi = -1e30f;
#pragma unroll
            for (int nt = 0; nt < 8; nt++) {
                tm_lo = fmaxf(tm_lo, fmaxf(sc[nt][0], sc[nt][1]));
                tm_hi = fmaxf(tm_hi, fmaxf(sc[nt][2], sc[nt][3]));
            }
            tm_lo = fmaxf(tm_lo, __shfl_xor_sync(0xffffffffu, tm_lo, 1));
            tm_lo = fmaxf(tm_lo, __shfl_xor_sync(0xffffffffu, tm_lo, 2));
            tm_hi = fmaxf(tm_hi, __shfl_xor_sync(0xffffffffu, tm_hi, 1));
            tm_hi = fmaxf(tm_hi, __shfl_xor_sync(0xffffffffu, tm_hi, 2));

            const float mn_lo = fmaxf(m_lo, tm_lo);
            const float mn_hi = fmaxf(m_hi, tm_hi);
            const float r_lo = __expf(m_lo - mn_lo);
            const float r_hi = __expf(m_hi - mn_hi);
            m_lo = mn_lo; m_hi = mn_hi;

            float sl = 0.f, sh = 0.f;
#pragma unroll
            for (int nt = 0; nt < 8; nt++) {
                sc[nt][0] = __expf(sc[nt][0] - mn_lo);
                sc[nt][1] = __expf(sc[nt][1] - mn_lo);
                sc[nt][2] = __expf(sc[nt][2] - mn_hi);
                sc[nt][3] = __expf(sc[nt][3] - mn_hi);
                sl += sc[nt][0] + sc[nt][1];
                sh += sc[nt][2] + sc[nt][3];
            }
            l_lo = l_lo * r_lo + sl;
            l_hi = l_hi * r_hi + sh;
#pragma unroll
            for (int j = 0; j < 16; j++) {
                o[j][0] *= r_lo; o[j][1] *= r_lo;
                o[j][2] *= r_hi; o[j][3] *= r_hi;
            }

#pragma unroll
            for (int t = 0; t < 4; t++) {
                uint32_t a[4] = {
                    packh2(sc[2 * t][0],     sc[2 * t][1]),
                    packh2(sc[2 * t][2],     sc[2 * t][3]),
                    packh2(sc[2 * t + 1][0], sc[2 * t + 1][1]),
                    packh2(sc[2 * t + 1][2], sc[2 * t + 1][3])
                };
#pragma unroll
                for (int dg = 0; dg < 8; dg++) {
                    uint32_t bv[4];
                    ldsm4t(bv, Vst + ((t * 16 + vKrow) * AP + dg * 16 + vDoff) * 2);
                    mma_f16(o[2 * dg],     a, bv[0], bv[1]);
                    mma_f16(o[2 * dg + 1], a, bv[2], bv[3]);
                }
            }
        }

        if (s < 7) { CP_WAIT0(); __syncthreads(); }
    }

    l_lo += __shfl_xor_sync(0xffffffffu, l_lo, 1);
    l_lo += __shfl_xor_sync(0xffffffffu, l_lo, 2);
    l_hi += __shfl_xor_sync(0xffffffffu, l_hi, 1);
    l_hi += __shfl_xor_sync(0xffffffffu, l_hi, 2);
    const float il = 1.0f / l_lo;
    const float ih = 1.0f / l_hi;

    __half* aop = AO + (size_t)(b * 4096 + qb * 64 + wr) * 2048 + h * 128;
#pragma unroll
    for (int j = 0; j < 16; j++) {
        const int col = j * 8 + 2 * lc;
        *(uint32_t*)(aop + (size_t)lr * 2048 + col)       = packh2(o[j][0] * il, o[j][1] * il);
        *(uint32_t*)(aop + (size_t)(lr + 8) * 2048 + col) = packh2(o[j][2] * ih, o[j][3] * ih);
    }
}

// ---------------------------------------------------------------------------
extern "C" void kernel_launch(void* const* d_in, const int* in_sizes, int n_in,
                              void* d_out, int out_size)
{
    const float* hidden = (const float*)d_in[0];
    const float* cosp   = (const float*)d_in[1];
    const float* sinp   = (const float*)d_in[2];
    const float* maskp  = (const float*)d_in[3];
    const float* Wq     = (const float*)d_in[4];
    const float* Wk     = (const float*)d_in[5];
    const float* Wv     = (const float*)d_in[6];
    const float* Wo     = (const float*)d_in[7];
    float* out = (float*)d_out;

    __half *Qh, *Kh, *Vh, *AOh, *Xh, *WqT, *WkT, *WvT, *WoT;
    cudaGetSymbolAddress((void**)&Qh, g_Qh);
    cudaGetSymbolAddress((void**)&Kh, g_Kh);
    cudaGetSymbolAddress((void**)&Vh, g_Vh);
    cudaGetSymbolAddress((void**)&AOh, g_AOh);
    cudaGetSymbolAddress((void**)&Xh, g_Xh);
    cudaGetSymbolAddress((void**)&WqT, g_WqT);
    cudaGetSymbolAddress((void**)&WkT, g_WkT);
    cudaGetSymbolAddress((void**)&WvT, g_WvT);
    cudaGetSymbolAddress((void**)&WoT, g_WoT);

    cudaFuncSetAttribute(attn_flash, cudaFuncAttributeMaxDynamicSharedMemorySize,
                         ATTN2_SMEM_BYTES);
    cudaFuncSetAttribute(gemm_qkv, cudaFuncAttributeMaxDynamicSharedMemorySize,
                         GSMH_BYTES);
    cudaFuncSetAttribute(gemm_wo, cudaFuncAttributeMaxDynamicSharedMemorySize,
                         GSMH_BYTES);

    // prep: hidden -> half; all 4 weight transposes in one launch
    const int n8 = 2 * 4096 * 2048 / 8;
    round_half<<<(n8 + 255) / 256, 256>>>(hidden, Xh, n8);
    transpose_all<<<dim3(64, 64, 4), dim3(32, 8)>>>(Wq, Wk, Wv, Wo, WqT, WkT, WvT, WoT);

    // fused QKV projections + RoPE
    gemm_qkv<<<dim3(24, 64), 128, GSMH_BYTES>>>(Xh, WqT, WkT, WvT, Qh, Kh, Vh, cosp, sinp);

    // flash-style fp16 block-sparse attention
    attn_flash<<<dim3(64, 16, 2), 128, ATTN2_SMEM_BYTES>>>(Qh, Kh, Vh, maskp, AOh);

    // output projection
    gemm_wo<<<dim3(16, 64), 128, GSMH_BYTES>>>(AOh, WoT, out, 8192, 2048, 2048);
}

// round 16
// speedup vs baseline: 1.0416x; 1.0416x over previous
#include <cuda_runtime.h>
#include <cuda_fp16.h>
#include <math.h>
#include <stdint.h>

// B=2, S=4096, HID=2048, H=16, KV=4, D=128, BS=64, L=4, G=4, STRIDE=4, WTOK=2048
#define NEGV (-1000000000.0f)
#define SCALEV 0.08838834764831845f   // 1/sqrt(128)

// ---------------- scratch (__device__ globals; allocation-free rule) -------
// Q/K stored in PERMUTED-d layout within each head: p=2j <-> d=j, p=2j+1 <-> d=j+64.
__device__ __align__(1024) __half g_Qh [2 * 4096 * 2048];
__device__ __align__(1024) __half g_Kh [2 * 4096 * 512];
__device__ __align__(1024) __half g_Vh [2 * 4096 * 512];
__device__ __align__(1024) __half g_AOh[2 * 4096 * 2048];
__device__ __align__(1024) __half g_Xh [2 * 4096 * 2048];
__device__ __align__(1024) __half g_WqT[2048 * 2048];
__device__ __align__(1024) __half g_WkT[512 * 2048];
__device__ __align__(1024) __half g_WvT[512 * 2048];
__device__ __align__(1024) __half g_WoT[2048 * 2048];

// ---------------- helpers ---------------------------------------------------
__device__ __forceinline__ uint32_t smem_u32(const void* p) {
    uint32_t a;
    asm("{ .reg .u64 t; cvta.to.shared.u64 t, %1; cvt.u32.u64 %0, t; }" : "=r"(a) : "l"(p));
    return a;
}
#define CP_ASYNC16(sm, gm) \
    asm volatile("cp.async.cg.shared.global [%0], [%1], 16;" :: "r"(sm), "l"(gm) : "memory")
#define CP_COMMIT() asm volatile("cp.async.commit_group;" ::: "memory")
#define CP_WAIT0()  asm volatile("cp.async.wait_group 0;" ::: "memory")
#define CP_WAIT1()  asm volatile("cp.async.wait_group 1;" ::: "memory")
#define CP_WAIT2()  asm volatile("cp.async.wait_group 2;" ::: "memory")

__device__ __forceinline__ void mma_f16(float c[4], const uint32_t a[4], uint32_t b0, uint32_t b1) {
    asm volatile(
        "mma.sync.aligned.m16n8k16.row.col.f32.f16.f16.f32 "
        "{%0,%1,%2,%3}, {%4,%5,%6,%7}, {%8,%9}, {%0,%1,%2,%3};"
        : "+f"(c[0]), "+f"(c[1]), "+f"(c[2]), "+f"(c[3])
        : "r"(a[0]), "r"(a[1]), "r"(a[2]), "r"(a[3]), "r"(b0), "r"(b1));
}
__device__ __forceinline__ void ldsm4(uint32_t r[4], uint32_t addr) {
    asm volatile("ldmatrix.sync.aligned.m8n8.x4.shared.b16 {%0,%1,%2,%3}, [%4];"
                 : "=r"(r[0]), "=r"(r[1]), "=r"(r[2]), "=r"(r[3]) : "r"(addr));
}
__device__ __forceinline__ void ldsm4t(uint32_t r[4], uint32_t addr) {
    asm volatile("ldmatrix.sync.aligned.m8n8.x4.trans.shared.b16 {%0,%1,%2,%3}, [%4];"
                 : "=r"(r[0]), "=r"(r[1]), "=r"(r[2]), "=r"(r[3]) : "r"(addr));
}
__device__ __forceinline__ uint32_t packh2(float x, float y) {
    __half2 h = __floats2half2_rn(x, y);
    return *(uint32_t*)&h;
}

// ---------------------------------------------------------------------------
// GEMM core (R13-measured config): 128x128 CTA tile, 4 warps, warp tile 64x64,
// BK=32, 4-stage cp.async. Pitch 40 halves (80B): conflict-free ldmatrix.
// ---------------------------------------------------------------------------
#define HP2  40
#define STGH (128 * HP2)
#define GSMH_BYTES (8 * STGH * 2)             // 81920 B

#define GLOADH(buf, k0)                                                                \
    do {                                                                               \
        _Pragma("unroll")                                                              \
        for (int it = 0; it < 4; it++) {                                               \
            const int row = ldrow + it * 32;                                           \
            const uint32_t so = (uint32_t)(((buf) * STGH + row * HP2 + ldc * 8) * 2);  \
            CP_ASYNC16(smbA + so, A  + (size_t)(crow0 + row) * K + (k0) + ldc * 8);    \
            CP_ASYNC16(smbB + so, Bt + (size_t)(ccol0 + row) * K + (k0) + ldc * 8);    \
        }                                                                              \
    } while (0)

#define GEMM_MAIN(T)                                                                   \
    GLOADH(0, 0);  CP_COMMIT();                                                        \
    GLOADH(1, 32); CP_COMMIT();                                                        \
    GLOADH(2, 64); CP_COMMIT();                                                        \
    for (int t = 0; t < (T); t++) {                                                    \
        const int rem = (T) - 1 - t;                                                   \
        if (rem >= 2) CP_WAIT2(); else if (rem == 1) CP_WAIT1(); else CP_WAIT0();      \
        __syncthreads();                                                               \
        if (t + 3 < (T)) { GLOADH((t + 3) & 3, (t + 3) << 5); CP_COMMIT(); }           \
        const int buf = t & 3;                                                         \
        const uint32_t Ab = smbA + buf * STGH * 2;                                     \
        const uint32_t Bb = smbB + buf * STGH * 2;                                     \
        _Pragma("unroll")                                                              \
        for (int kk = 0; kk < 2; kk++) {                                               \
            uint32_t a[4][4];                                                          \
            _Pragma("unroll")                                                          \
            for (int mt = 0; mt < 4; mt++)                                             \
                ldsm4(a[mt], Ab + ((aRowBase + mt * 16) * HP2 + kk * 16 + aKoff) * 2); \
            uint32_t br[4][4];                                                         \
            _Pragma("unroll")                                                          \
            for (int g = 0; g < 4; g++)                                                \
                ldsm4(br[g], Bb + ((bRowBase + g * 16) * HP2 + kk * 16 + bKoff) * 2);  \
            _Pragma("unroll")                                                          \
            for (int mt = 0; mt < 4; mt++)                                             \
                _Pragma("unroll")                                                      \
                for (int nt = 0; nt < 8; nt++)                                         \
                    mma_f16(acc[mt][nt], a[mt], br[nt >> 1][(nt & 1) * 2],             \
                            br[nt >> 1][(nt & 1) * 2 + 1]);                            \
        }                                                                              \
    }

// ---------------------------------------------------------------------------
// Fused QKV projection GEMM + RoPE epilogue (Q,K regions; V plain).
// grid.x: 0-15 Q | 16-19 K | 20-23 V. grid.y: 64 row tiles. 128 threads.
// ---------------------------------------------------------------------------
__global__ __launch_bounds__(128, 2) void gemm_qkv(
    const __half* __restrict__ A,
    const __half* __restrict__ WqT_, const __half* __restrict__ WkT_,
    const __half* __restrict__ WvT_,
    __half* __restrict__ Qh, __half* __restrict__ Kh, __half* __restrict__ Vh,
    const float* __restrict__ cosp, const float* __restrict__ sinp)
{
    extern __shared__ __half smh[];
    const uint32_t smbA = smem_u32(smh);
    const uint32_t smbB = smbA + 4 * STGH * 2;

    const int bx = blockIdx.x;
    const __half* Bt;
    __half* C;
    int Nc, ccol0;
    bool rope;
    if (bx < 16)      { Bt = WqT_; C = Qh; Nc = 2048; ccol0 = bx * 128;        rope = true;  }
    else if (bx < 20) { Bt = WkT_; C = Kh; Nc = 512;  ccol0 = (bx - 16) * 128; rope = true;  }
    else              { Bt = WvT_; C = Vh; Nc = 512;  ccol0 = (bx - 20) * 128; rope = false; }
    const int K = 2048;

    const int tid  = threadIdx.x;
    const int lane = tid & 31;
    const int warp = tid >> 5;
    const int wm = warp & 1;
    const int wn = warp >> 1;
    const int lr = lane >> 2;
    const int lc = lane & 3;
    const int crow0 = blockIdx.y * 128;

    const int ldrow = tid >> 2;
    const int ldc   = tid & 3;

    float acc[4][8][4];
#pragma unroll
    for (int mt = 0; mt < 4; mt++)
#pragma unroll
        for (int nt = 0; nt < 8; nt++)
#pragma unroll
            for (int i = 0; i < 4; i++) acc[mt][nt][i] = 0.f;

    const int aRowBase = wm * 64 + (lane & 15);
    const int aKoff    = (lane >> 4) * 8;
    const int bRowBase = wn * 64 + (lane & 7) + ((lane >> 4) & 1) * 8;
    const int bKoff    = ((lane >> 3) & 1) * 8;

    GEMM_MAIN(64)

    if (rope) {
#pragma unroll
        for (int mt = 0; mt < 4; mt++) {
            const int r0 = crow0 + wm * 64 + mt * 16 + lr;
#pragma unroll
            for (int nt = 0; nt < 8; nt++) {
                const int col = ccol0 + wn * 64 + nt * 8 + 2 * lc;
                const int d = (col & 127) >> 1;
                {
                    const float c1 = __ldg(cosp + (size_t)r0 * 128 + d);
                    const float s1 = __ldg(sinp + (size_t)r0 * 128 + d);
                    const float c2 = __ldg(cosp + (size_t)r0 * 128 + d + 64);
                    const float s2 = __ldg(sinp + (size_t)r0 * 128 + d + 64);
                    const float a0 = acc[mt][nt][0], a1 = acc[mt][nt][1];
                    *(uint32_t*)(C + (size_t)r0 * Nc + col) =
                        packh2(a0 * c1 - a1 * s1, a1 * c2 + a0 * s2);
                }
                {
                    const int r1 = r0 + 8;
                    const float c1 = __ldg(cosp + (size_t)r1 * 128 + d);
                    const float s1 = __ldg(sinp + (size_t)r1 * 128 + d);
                    const float c2 = __ldg(cosp + (size_t)r1 * 128 + d + 64);
                    const float s2 = __ldg(sinp + (size_t)r1 * 128 + d + 64);
                    const float a0 = acc[mt][nt][2], a1 = acc[mt][nt][3];
                    *(uint32_t*)(C + (size_t)r1 * Nc + col) =
                        packh2(a0 * c1 - a1 * s1, a1 * c2 + a0 * s2);
                }
            }
        }
    } else {
#pragma unroll
        for (int mt = 0; mt < 4; mt++) {
            const int row = crow0 + wm * 64 + mt * 16 + lr;
#pragma unroll
            for (int nt = 0; nt < 8; nt++) {
                const int col = ccol0 + wn * 64 + nt * 8 + 2 * lc;
                *(uint32_t*)(C + (size_t)row * Nc + col)       = packh2(acc[mt][nt][0], acc[mt][nt][1]);
                *(uint32_t*)(C + (size_t)(row + 8) * Nc + col) = packh2(acc[mt][nt][2], acc[mt][nt][3]);
            }
        }
    }
}

// ---------------------------------------------------------------------------
// Output projection GEMM (fp32 out).
// ---------------------------------------------------------------------------
__global__ __launch_bounds__(128, 2) void gemm_wo(
    const __half* __restrict__ A, const __half* __restrict__ Bt, float* __restrict__ C,
    int M, int N, int K)
{
    extern __shared__ __half smh[];
    const uint32_t smbA = smem_u32(smh);
    const uint32_t smbB = smbA + 4 * STGH * 2;

    const int tid  = threadIdx.x;
    const int lane = tid & 31;
    const int warp = tid >> 5;
    const int wm = warp & 1;
    const int wn = warp >> 1;
    const int lr = lane >> 2;
    const int lc = lane & 3;
    const int crow0 = blockIdx.y * 128;
    const int ccol0 = blockIdx.x * 128;

    const int ldrow = tid >> 2;
    const int ldc   = tid & 3;

    float acc[4][8][4];
#pragma unroll
    for (int mt = 0; mt < 4; mt++)
#pragma unroll
        for (int nt = 0; nt < 8; nt++)
#pragma unroll
            for (int i = 0; i < 4; i++) acc[mt][nt][i] = 0.f;

    const int aRowBase = wm * 64 + (lane & 15);
    const int aKoff    = (lane >> 4) * 8;
    const int bRowBase = wn * 64 + (lane & 7) + ((lane >> 4) & 1) * 8;
    const int bKoff    = ((lane >> 3) & 1) * 8;

    const int T = K >> 5;
    GEMM_MAIN(T)

#pragma unroll
    for (int mt = 0; mt < 4; mt++) {
        const int row = crow0 + wm * 64 + mt * 16 + lr;
#pragma unroll
        for (int nt = 0; nt < 8; nt++) {
            const int col = ccol0 + wn * 64 + nt * 8 + 2 * lc;
            *(float2*)(C + (size_t)row * N + col)       = make_float2(acc[mt][nt][0], acc[mt][nt][1]);
            *(float2*)(C + (size_t)(row + 8) * N + col) = make_float2(acc[mt][nt][2], acc[mt][nt][3]);
        }
    }
}

// ---------------------------------------------------------------------------
// prep kernels
// ---------------------------------------------------------------------------
__global__ void round_half(const float* __restrict__ src, __half* __restrict__ dst, int n8) {
    int i = blockIdx.x * blockDim.x + threadIdx.x;
    if (i < n8) {
        float4 v0 = ((const float4*)src)[2 * i];
        float4 v1 = ((const float4*)src)[2 * i + 1];
        uint4 o;
        o.x = packh2(v0.x, v0.y); o.y = packh2(v0.z, v0.w);
        o.z = packh2(v1.x, v1.y); o.w = packh2(v1.z, v1.w);
        ((uint4*)dst)[i] = o;
    }
}
// All four weight transposes in one launch. blockIdx.z: 0=Wq(perm) 1=Wk(perm)
// 2=Wv 3=Wo.
__global__ void transpose_all(const float* __restrict__ Wq, const float* __restrict__ Wk,
                              const float* __restrict__ Wv, const float* __restrict__ Wo,
                              __half* __restrict__ WqT, __half* __restrict__ WkT,
                              __half* __restrict__ WvT, __half* __restrict__ WoT)
{
    const int z = blockIdx.z;
    const float* W; __half* Wt; int N; bool perm;
    if (z == 0)      { W = Wq; Wt = WqT; N = 2048; perm = true;  }
    else if (z == 1) { W = Wk; Wt = WkT; N = 512;  perm = true;  }
    else if (z == 2) { W = Wv; Wt = WvT; N = 512;  perm = false; }
    else             { W = Wo; Wt = WoT; N = 2048; perm = false; }
    const int K = 2048;
    if (blockIdx.x * 32 >= N) return;

    __shared__ float t[32][33];
    const int n0 = blockIdx.x * 32, k0 = blockIdx.y * 32;
    const int x = threadIdx.x, y = threadIdx.y;
#pragma unroll
    for (int j = 0; j < 32; j += 8)
        t[y + j][x] = W[(size_t)(k0 + y + j) * N + n0 + x];
    __syncthreads();
#pragma unroll
    for (int j = 0; j < 32; j += 8) {
        const int n = n0 + y + j;
        int npr = n;
        if (perm) {
            const int d = n & 127;
            const int p = (d < 64) ? (2 * d) : (2 * (d - 64) + 1);
            npr = (n & ~127) | p;
        }
        Wt[(size_t)npr * K + k0 + x] = __float2half_rn(t[x][y + j]);
    }
}

// ---------------------------------------------------------------------------
// Flash-style fp16 block-sparse attention with software-pipelined fragment
// loads (ldsm one step ahead of consuming mma). Structure otherwise R13.
// ---------------------------------------------------------------------------
#define AP    136
#define ATILE (64 * AP)
#define SQ_H  0
#define SK_H  ATILE
#define SV_H  (SK_H + 2 * ATILE)
#define ATTN2_SMEM_BYTES ((SV_H + 2 * ATILE) * 2)   // 87040 B

__global__ __launch_bounds__(128, 2) void attn_flash(
    const __half* __restrict__ Q, const __half* __restrict__ K, const __half* __restrict__ V,
    const float* __restrict__ mask, __half* __restrict__ AO)
{
    extern __shared__ __half smA[];
    const uint32_t Qaddr = smem_u32(smA + SQ_H);
    const uint32_t Kaddr = smem_u32(smA + SK_H);
    const uint32_t Vaddr = smem_u32(smA + SV_H);

    const int qb = blockIdx.x;
    const int h  = blockIdx.y;
    const int b  = blockIdx.z;
    const int kvh = h >> 2;
    const int tid = threadIdx.x;
    const int lane = tid & 31;
    const int warp = tid >> 5;
    const int lr = lane >> 2;
    const int lc = lane & 3;
    const int wr = warp * 16;

    int kblk[8]; bool kvalid[8];
#pragma unroll
    for (int w = 0; w < 4; w++) {
        int jb = qb - 3 + w;
        kblk[w] = jb < 0 ? 0 : jb;
        kvalid[w] = (jb >= 0);
    }
    {
        int start = qb - 32; if (start < 0) start = 0;
        int cnt = (qb > start) ? ((qb - start + 3) >> 2) : 0;
        int first = (cnt > 4) ? (cnt - 4) : 0;
        int sz = (cnt < 4) ? cnt : 4;
        int s0 = 4 - sz;
#pragma unroll
        for (int g = 0; g < 4; g++) {
            if (g < s0) { kblk[4 + g] = 0; kvalid[4 + g] = false; }
            else        { kblk[4 + g] = start + 4 * (first + g - s0); kvalid[4 + g] = true; }
        }
    }

    const __half* Qsrc  = Q + (size_t)(b * 4096 + qb * 64) * 2048 + h * 128;
    const __half* Kbase = K + (size_t)b * 4096 * 512 + kvh * 128;
    const __half* Vbase = V + (size_t)b * 4096 * 512 + kvh * 128;

#define AKV_ISSUE(stage, blk)                                                          \
    do {                                                                               \
        const __half* ksrc = Kbase + (size_t)(blk) * 64 * 512;                         \
        const __half* vsrc = Vbase + (size_t)(blk) * 64 * 512;                         \
        _Pragma("unroll")                                                              \
        for (int it = 0; it < 8; it++) {                                               \
            const int f = tid + it * 128;                                              \
            const int row = f >> 4, c8 = f & 15;                                       \
            const uint32_t so = (stage) * (ATILE * 2) + (row * AP + c8 * 8) * 2;       \
            CP_ASYNC16(Kaddr + so, ksrc + (size_t)row * 512 + c8 * 8);                 \
            CP_ASYNC16(Vaddr + so, vsrc + (size_t)row * 512 + c8 * 8);                 \
        }                                                                              \
    } while (0)

#pragma unroll
    for (int it = 0; it < 8; it++) {
        const int f = tid + it * 128;
        const int row = f >> 4, c8 = f & 15;
        CP_ASYNC16(Qaddr + (row * AP + c8 * 8) * 2, Qsrc + (size_t)row * 2048 + c8 * 8);
    }
    AKV_ISSUE(0, kblk[0]);
    CP_COMMIT();
    CP_WAIT0();
    __syncthreads();

    uint32_t qf[8][4];
    const int aRow  = wr + (lane & 15);
    const int aKoff = (lane >> 4) * 8;
#pragma unroll
    for (int kk = 0; kk < 8; kk++)
        ldsm4(qf[kk], Qaddr + (aRow * AP + kk * 16 + aKoff) * 2);

    float o[16][4];
#pragma unroll
    for (int j = 0; j < 16; j++)
#pragma unroll
        for (int i = 0; i < 4; i++) o[j][i] = 0.f;
    float m_lo = -1e30f, m_hi = -1e30f, l_lo = 0.f, l_hi = 0.f;

    const int bRow  = (lane & 7) + ((lane >> 4) & 1) * 8;
    const int bKoff = ((lane >> 3) & 1) * 8;
    const int vKrow = (lane & 7) + ((lane >> 3) & 1) * 8;
    const int vDoff = ((lane >> 4) & 1) * 8;
    const int row_lo = wr + lr;

    for (int s = 0; s < 8; s++) {
        if (s < 7) { AKV_ISSUE((s + 1) & 1, kblk[s + 1]); CP_COMMIT(); }

        if (kvalid[s]) {
            const uint32_t Kst = Kaddr + (s & 1) * (ATILE * 2);
            const uint32_t Vst = Vaddr + (s & 1) * (ATILE * 2);

            // ---- QK^T with br double-buffer (ldsm 1 kk ahead of mma) ----
            float sc[8][4];
#pragma unroll
            for (int nt = 0; nt < 8; nt++)
#pragma unroll
                for (int i = 0; i < 4; i++) sc[nt][i] = 0.f;

            uint32_t brA[4][4], brB[4][4];
#pragma unroll
            for (int g = 0; g < 4; g++)
                ldsm4(brA[g], Kst + ((g * 16 + bRow) * AP + 0 + bKoff) * 2);
#pragma unroll
            for (int kk = 0; kk < 8; kk++) {
                uint32_t (*cur)[4] = (kk & 1) ? brB : brA;
                uint32_t (*nxt)[4] = (kk & 1) ? brA : brB;
                if (kk < 7) {
#pragma unroll
                    for (int g = 0; g < 4; g++)
                        ldsm4(nxt[g], Kst + ((g * 16 + bRow) * AP + (kk + 1) * 16 + bKoff) * 2);
                }
#pragma unroll
                for (int nt = 0; nt < 8; nt++)
                    mma_f16(sc[nt], qf[kk], cur[nt >> 1][(nt & 1) * 2], cur[nt >> 1][(nt & 1) * 2 + 1]);
            }

            const float* mrow = mask + (size_t)b * 4096 + kblk[s] * 64;
            const bool cz = (s == 3);
#pragma unroll
            for (int nt = 0; nt < 8; nt++) {
                const int c0 = nt * 8 + 2 * lc;
                const float mv0 = (1.0f - __ldg(mrow + c0)) * NEGV;
                const float mv1 = (1.0f - __ldg(mrow + c0 + 1)) * NEGV;
                sc[nt][0] = sc[nt][0] * SCALEV + mv0;
                sc[nt][1] = sc[nt][1] * SCALEV + mv1;
                sc[nt][2] = sc[nt][2] * SCALEV + mv0;
                sc[nt][3] = sc[nt][3] * SCALEV + mv1;
                if (cz) {
                    if (c0     > row_lo)     sc[nt][0] += NEGV;
                    if (c0 + 1 > row_lo)     sc[nt][1] += NEGV;
                    if (c0     > row_lo + 8) sc[nt][2] += NEGV;
                    if (c0 + 1 > row_lo + 8) sc[nt][3] += NEGV;
                }
            }

            float tm_lo = -1e30f, tm_hi = -1e30f;
#pragma unroll
            for (int nt = 0; nt < 8; nt++) {
                tm_lo = fmaxf(tm_lo, fmaxf(sc[nt][0], sc[nt][1]));
                tm_hi = fmaxf(tm_hi, fmaxf(sc[nt][2], sc[nt][3]));
            }
            tm_lo = fmaxf(tm_lo, __shfl_xor_sync(0xffffffffu, tm_lo, 1));
            tm_lo = fmaxf(tm_lo, __shfl_xor_sync(0xffffffffu, tm_lo, 2));
            tm_hi = fmaxf(tm_hi, __shfl_xor_sync(0xffffffffu, tm_hi, 1));
            tm_hi = fmaxf(tm_hi, __shfl_xor_sync(0xffffffffu, tm_hi, 2));

            const float mn_lo = fmaxf(m_lo, tm_lo);
            const float mn_hi = fmaxf(m_hi, tm_hi);
            const float r_lo = __expf(m_lo - mn_lo);
            const float r_hi = __expf(m_hi - mn_hi);
            m_lo = mn_lo; m_hi = mn_hi;

            float sl = 0.f, sh = 0.f;
#pragma unroll
            for (int nt = 0; nt < 8; nt++) {
                sc[nt][0] = __expf(sc[nt][0] - mn_lo);
                sc[nt][1] = __expf(sc[nt][1] - mn_lo);
                sc[nt][2] = __expf(sc[nt][2] - mn_hi);
                sc[nt][3] = __expf(sc[nt][3] - mn_hi);
                sl += sc[nt][0] + sc[nt][1];
                sh += sc[nt][2] + sc[nt][3];
            }
            l_lo = l_lo * r_lo + sl;
            l_hi = l_hi * r_hi + sh;
#pragma unroll
            for (int j = 0; j < 16; j++) {
                o[j][0] *= r_lo; o[j][1] *= r_lo;
                o[j][2] *= r_hi; o[j][3] *= r_hi;
            }

            // ---- PV with bv double-buffer (ldsm4t 1 dg ahead of mma) ----
#pragma unroll
            for (int t = 0; t < 4; t++) {
                uint32_t a[4] = {
                    packh2(sc[2 * t][0],     sc[2 * t][1]),
                    packh2(sc[2 * t][2],     sc[2 * t][3]),
                    packh2(sc[2 * t + 1][0], sc[2 * t + 1][1]),
                    packh2(sc[2 * t + 1][2], sc[2 * t + 1][3])
                };
                uint32_t bvA[4], bvB[4];
                ldsm4t(bvA, Vst + ((t * 16 + vKrow) * AP + 0 + vDoff) * 2);
#pragma unroll
                for (int dg = 0; dg < 8; dg++) {
                    uint32_t* cur = (dg & 1) ? bvB : bvA;
                    uint32_t* nxt = (dg & 1) ? bvA : bvB;
                    if (dg < 7)
                        ldsm4t(nxt, Vst + ((t * 16 + vKrow) * AP + (dg + 1) * 16 + vDoff) * 2);
                    mma_f16(o[2 * dg],     a, cur[0], cur[1]);
                    mma_f16(o[2 * dg + 1], a, cur[2], cur[3]);
                }
            }
        }

        if (s < 7) { CP_WAIT0(); __syncthreads(); }
    }

    l_lo += __shfl_xor_sync(0xffffffffu, l_lo, 1);
    l_lo += __shfl_xor_sync(0xffffffffu, l_lo, 2);
    l_hi += __shfl_xor_sync(0xffffffffu, l_hi, 1);
    l_hi += __shfl_xor_sync(0xffffffffu, l_hi, 2);
    const float il = 1.0f / l_lo;
    const float ih = 1.0f / l_hi;

    __half* aop = AO + (size_t)(b * 4096 + qb * 64 + wr) * 2048 + h * 128;
#pragma unroll
    for (int j = 0; j < 16; j++) {
        const int col = j * 8 + 2 * lc;
        *(uint32_t*)(aop + (size_t)lr * 2048 + col)       = packh2(o[j][0] * il, o[j][1] * il);
        *(uint32_t*)(aop + (size_t)(lr + 8) * 2048 + col) = packh2(o[j][2] * ih, o[j][3] * ih);
    }
}

// ---------------------------------------------------------------------------
extern "C" void kernel_launch(void* const* d_in, const int* in_sizes, int n_in,
                              void* d_out, int out_size)
{
    const float* hidden = (const float*)d_in[0];
    const float* cosp   = (const float*)d_in[1];
    const float* sinp   = (const float*)d_in[2];
    const float* maskp  = (const float*)d_in[3];
    const float* Wq     = (const float*)d_in[4];
    const float* Wk     = (const float*)d_in[5];
    const float* Wv     = (const float*)d_in[6];
    const float* Wo     = (const float*)d_in[7];
    float* out = (float*)d_out;

    __half *Qh, *Kh, *Vh, *AOh, *Xh, *WqT, *WkT, *WvT, *WoT;
    cudaGetSymbolAddress((void**)&Qh, g_Qh);
    cudaGetSymbolAddress((void**)&Kh, g_Kh);
    cudaGetSymbolAddress((void**)&Vh, g_Vh);
    cudaGetSymbolAddress((void**)&AOh, g_AOh);
    cudaGetSymbolAddress((void**)&Xh, g_Xh);
    cudaGetSymbolAddress((void**)&WqT, g_WqT);
    cudaGetSymbolAddress((void**)&WkT, g_WkT);
    cudaGetSymbolAddress((void**)&WvT, g_WvT);
    cudaGetSymbolAddress((void**)&WoT, g_WoT);

    cudaFuncSetAttribute(attn_flash, cudaFuncAttributeMaxDynamicSharedMemorySize,
                         ATTN2_SMEM_BYTES);
    cudaFuncSetAttribute(gemm_qkv, cudaFuncAttributeMaxDynamicSharedMemorySize,
                         GSMH_BYTES);
    cudaFuncSetAttribute(gemm_wo, cudaFuncAttributeMaxDynamicSharedMemorySize,
                         GSMH_BYTES);

    // prep: hidden -> half; all 4 weight transposes in one launch
    const int n8 = 2 * 4096 * 2048 / 8;
    round_half<<<(n8 + 255) / 256, 256>>>(hidden, Xh, n8);
    transpose_all<<<dim3(64, 64, 4), dim3(32, 8)>>>(Wq, Wk, Wv, Wo, WqT, WkT, WvT, WoT);

    // fused QKV projections + RoPE
    gemm_qkv<<<dim3(24, 64), 128, GSMH_BYTES>>>(Xh, WqT, WkT, WvT, Qh, Kh, Vh, cosp, sinp);

    // flash-style fp16 block-sparse attention
    attn_flash<<<dim3(64, 16, 2), 128, ATTN2_SMEM_BYTES>>>(Qh, Kh, Vh, maskp, AOh);

    // output projection
    gemm_wo<<<dim3(16, 64), 128, GSMH_BYTES>>>(AOh, WoT, out, 8192, 2048, 2048);
}